// round 6
// baseline (speedup 1.0000x reference)
#include <cuda_runtime.h>
#include <cuda_bf16.h>
#include <cstdint>

// Problem constants
#define NN   32
#define CC   512
#define TT   1024
#define NTOK 32768            // NN*TT
#define NB   2048
#define MU   0.99f
#define OMU  0.01f

// Output layout (concatenated, all f32)
#define OFF_XD    ((size_t)0)
#define OFF_LOSS  ((size_t)16777216)
#define OFF_PERP  ((size_t)16777217)
#define OFF_CB    ((size_t)16777218)
#define OFF_SEMA  ((size_t)17825794)
#define OFF_CEMA  ((size_t)18874370)

// ---------------- device scratch (no allocs allowed) ----------------
__device__ float g_cbnorm[NB];
__device__ float g_sum[(size_t)NB * CC];
__device__ float g_cnt[NB];
__device__ float g_loss;
__device__ __align__(16) __nv_bfloat16 g_xhi[(size_t)NTOK * CC];
__device__ __align__(16) __nv_bfloat16 g_xlo[(size_t)NTOK * CC];
__device__ __align__(16) __nv_bfloat16 g_bhi[(size_t)NB * CC];
__device__ __align__(16) __nv_bfloat16 g_blo[(size_t)NB * CC];

// ---------------- PTX helpers (arch-neutral: sm_80-era features only) ----
__device__ __forceinline__ uint32_t smem_u32(const void* p) {
    uint32_t a;
    asm("{ .reg .u64 t; cvta.to.shared.u64 t, %1; cvt.u32.u64 %0, t; }" : "=r"(a) : "l"(p));
    return a;
}
__device__ __forceinline__ void cp16(uint32_t dst, const void* src) {
    asm volatile("cp.async.cg.shared.global [%0], [%1], 16;" :: "r"(dst), "l"(src));
}
__device__ __forceinline__ void ldmx4(uint32_t* r, uint32_t addr) {
    asm volatile("ldmatrix.sync.aligned.m8n8.x4.shared.b16 {%0,%1,%2,%3}, [%4];"
                 : "=r"(r[0]), "=r"(r[1]), "=r"(r[2]), "=r"(r[3]) : "r"(addr));
}
__device__ __forceinline__ void mma16816(float* d, const uint32_t* a, const uint32_t* b) {
    asm volatile(
        "mma.sync.aligned.m16n8k16.row.col.f32.bf16.bf16.f32 "
        "{%0,%1,%2,%3}, {%4,%5,%6,%7}, {%8,%9}, {%0,%1,%2,%3};"
        : "+f"(d[0]), "+f"(d[1]), "+f"(d[2]), "+f"(d[3])
        : "r"(a[0]), "r"(a[1]), "r"(a[2]), "r"(a[3]), "r"(b[0]), "r"(b[1]));
}

// ---------------- zero scratch ----------------
__global__ void k_zero() {
    int i = blockIdx.x * blockDim.x + threadIdx.x;
    const int total = NB * CC + NB + 1;
    for (; i < total; i += gridDim.x * blockDim.x) {
        if (i < NB * CC)           g_sum[i] = 0.0f;
        else if (i < NB * CC + NB) g_cnt[i - NB * CC] = 0.0f;
        else                       g_loss = 0.0f;
    }
}

// ---------------- codebook: bf16 hi/lo split + exact fp32 norms ----------
__global__ __launch_bounds__(256) void k_convert_cb(const float* __restrict__ cb) {
    int wid  = (blockIdx.x * blockDim.x + threadIdx.x) >> 5;
    int lane = threadIdx.x & 31;
    if (wid >= NB) return;
    const float* row = cb + (size_t)wid * CC;
    float s = 0.0f;
    #pragma unroll
    for (int i = 0; i < CC / 32; i++) {
        float v = row[lane + 32 * i];
        s += v * v;
        __nv_bfloat16 hi = __float2bfloat16(v);
        g_bhi[(size_t)wid * CC + lane + 32 * i] = hi;
        g_blo[(size_t)wid * CC + lane + 32 * i] = __float2bfloat16(v - __bfloat162float(hi));
    }
    #pragma unroll
    for (int o = 16; o > 0; o >>= 1) s += __shfl_down_sync(0xFFFFFFFFu, s, o);
    if (lane == 0) g_cbnorm[wid] = s;
}

// ---------------- transpose + bf16 hi/lo split of x ----------------
__global__ __launch_bounds__(256) void k_convert_x(const float* __restrict__ x) {
    __shared__ float s[64][65];
    const int b = blockIdx.x;
    const int ttile = b & 15, ctile = (b >> 4) & 7, n = b >> 7;
    const int c0 = ctile * 64, t0 = ttile * 64;
    const int tid = threadIdx.x;
    const float* xb = x + (size_t)n * CC * TT;
    #pragma unroll
    for (int q = 0; q < 16; q++) {
        int idx = tid + 256 * q;
        int r = idx >> 6, col = idx & 63;
        s[r][col] = xb[(size_t)(c0 + r) * TT + t0 + col];
    }
    __syncthreads();
    #pragma unroll
    for (int q = 0; q < 16; q++) {
        int idx = tid + 256 * q;
        int tr = idx >> 6, cc = idx & 63;
        float v = s[cc][tr];
        __nv_bfloat16 hi = __float2bfloat16(v);
        __nv_bfloat16 lo = __float2bfloat16(v - __bfloat162float(hi));
        size_t token = (size_t)(n * 1024 + t0 + tr);
        g_xhi[token * 512 + c0 + cc] = hi;
        g_xlo[token * 512 + c0 + cc] = lo;
    }
}

// ---------------- mma.sync GEMM + fused argmin + fused scatter ----------
// Block: 128 tokens x 128-code tile, 16 code tiles, K' = 3*512 = 1536.
// 8 warps (2 x 4), warp tile 64x32. 3-stage cp.async ring, BK = 64.
// Double-buffered ldmatrix fragments: issue kk+1 loads before kk MMAs.
// Argmin folded per-nj via shared atomicMin (no per-thread best regs).
#define STAGE 32768
#define HMMA_SMEM (3 * STAGE)
#define NSTEPS 384              // 16 nj * 24 k-steps

__device__ __forceinline__ void load_tile(int tid, uint32_t dyn, int it, int m0) {
    const int nj = it / 24;
    const int kt = it - nj * 24;
    const int seg = kt >> 3;
    const int kke = (kt & 7) << 6;    // k element offset within 512
    const __nv_bfloat16* Asrc = ((seg < 2) ? g_xhi : g_xlo) + (size_t)m0 * 512 + kke;
    const __nv_bfloat16* Bsrc = ((seg == 1) ? g_blo : g_bhi) + (size_t)nj * 128 * 512 + kke;
    const uint32_t abase = dyn + (uint32_t)(it % 3) * STAGE;
    const uint32_t bbase = abase + 16384u;
    #pragma unroll
    for (int q = 0; q < 4; q++) {
        int op = tid + 256 * q;
        int row = op >> 3, c = op & 7;
        cp16(abase + row * 128 + (((c ^ row) & 7) << 4), Asrc + (size_t)row * 512 + c * 8);
    }
    #pragma unroll
    for (int q = 0; q < 4; q++) {
        int op = tid + 256 * q;
        int row = op >> 3, c = op & 7;
        cp16(bbase + row * 128 + (((c ^ row) & 7) << 4), Bsrc + (size_t)row * 512 + c * 8);
    }
    asm volatile("cp.async.commit_group;" ::: "memory");
}

__global__ __launch_bounds__(256, 2) void k_hmma(const float* __restrict__ x,
                                                 const float* __restrict__ cb,
                                                 float* __restrict__ out) {
    extern __shared__ char dsm[];
    __shared__ unsigned long long sKey[128];
    __shared__ int   sIdx[128];
    __shared__ float sRed[256];
    const uint32_t dyn = smem_u32(dsm);
    const int tid  = threadIdx.x;
    const int lane = tid & 31;
    const int warp = tid >> 5;
    const int wm   = warp >> 2;      // 0..1
    const int wn   = warp & 3;       // 0..3
    const int m0   = blockIdx.x * 128;

    // ldmatrix per-thread addressing
    const int sub = lane >> 3, l7 = lane & 7;
    const int a_rowadd = ((sub & 1) << 3) + l7;
    const int a_cadd   = sub >> 1;
    const int b_rowadd = ((sub >> 1) << 3) + l7;
    const int b_cadd   = sub & 1;
    uint32_t aRowB[4], bRowB[2];
    #pragma unroll
    for (int mt = 0; mt < 4; mt++) aRowB[mt] = (uint32_t)(wm * 64 + mt * 16 + a_rowadd) * 128u;
    #pragma unroll
    for (int p = 0; p < 2; p++)    bRowB[p] = (uint32_t)(wn * 32 + p * 16 + b_rowadd) * 128u;

    float acc[4][4][4];
    #pragma unroll
    for (int mt = 0; mt < 4; mt++)
        #pragma unroll
        for (int nt = 0; nt < 4; nt++)
            #pragma unroll
            for (int r = 0; r < 4; r++) acc[mt][nt][r] = 0.0f;

    if (tid < 128) sKey[tid] = 0xFFFFFFFFFFFFFFFFULL;

    load_tile(tid, dyn, 0, m0);
    load_tile(tid, dyn, 1, m0);

    for (int it = 0; it < NSTEPS; it++) {
        if (it + 1 < NSTEPS) asm volatile("cp.async.wait_group 1;" ::: "memory");
        else                 asm volatile("cp.async.wait_group 0;" ::: "memory");
        __syncthreads();
        if (it + 2 < NSTEPS) load_tile(tid, dyn, it + 2, m0);

        const uint32_t abase = dyn + (uint32_t)(it % 3) * STAGE;
        const uint32_t bbase = abase + 16384u;

        // double-buffered fragments across kk
        uint32_t afr[2][4][4], bfr[2][2][4];
        #pragma unroll
        for (int mt = 0; mt < 4; mt++)
            ldmx4(afr[0][mt], abase + aRowB[mt] + (((a_cadd ^ l7) & 7) << 4));
        #pragma unroll
        for (int p = 0; p < 2; p++)
            ldmx4(bfr[0][p], bbase + bRowB[p] + (((b_cadd ^ l7) & 7) << 4));

        #pragma unroll
        for (int kk = 0; kk < 4; kk++) {
            const int cur = kk & 1, nxt = cur ^ 1;
            if (kk < 3) {
                #pragma unroll
                for (int mt = 0; mt < 4; mt++)
                    ldmx4(afr[nxt][mt],
                          abase + aRowB[mt] + (((((kk + 1) * 2 + a_cadd) ^ l7) & 7) << 4));
                #pragma unroll
                for (int p = 0; p < 2; p++)
                    ldmx4(bfr[nxt][p],
                          bbase + bRowB[p] + (((((kk + 1) * 2 + b_cadd) ^ l7) & 7) << 4));
            }
            #pragma unroll
            for (int mt = 0; mt < 4; mt++)
                #pragma unroll
                for (int nt = 0; nt < 4; nt++)
                    mma16816(acc[mt][nt], afr[cur][mt], &bfr[cur][nt >> 1][(nt & 1) * 2]);
        }

        // end of one nj code-tile: fold argmin into sKey, reset acc
        if (it % 24 == 23) {
            const int njbase = (it / 24) * 128;
            #pragma unroll
            for (int mt = 0; mt < 4; mt++) {
                #pragma unroll
                for (int rh = 0; rh < 2; rh++) {
                    unsigned long long b = 0xFFFFFFFFFFFFFFFFULL;
                    #pragma unroll
                    for (int nt = 0; nt < 4; nt++) {
                        #pragma unroll
                        for (int c = 0; c < 2; c++) {
                            int j = njbase + wn * 32 + nt * 8 + ((lane & 3) << 1) + c;
                            float d = fmaf(-2.0f, acc[mt][nt][rh * 2 + c], __ldg(&g_cbnorm[j]));
                            unsigned u = __float_as_uint(d);
                            u = (u & 0x80000000u) ? ~u : (u | 0x80000000u);
                            unsigned long long key =
                                ((unsigned long long)u << 32) | (unsigned)j;
                            b = min(b, key);
                        }
                    }
                    b = min(b, __shfl_xor_sync(0xFFFFFFFFu, b, 1));
                    b = min(b, __shfl_xor_sync(0xFFFFFFFFu, b, 2));
                    if ((lane & 3) == 0) {
                        int row = wm * 64 + mt * 16 + (lane >> 2) + rh * 8;
                        atomicMin(&sKey[row], b);
                    }
                }
            }
            #pragma unroll
            for (int mt = 0; mt < 4; mt++)
                #pragma unroll
                for (int nt = 0; nt < 4; nt++)
                    #pragma unroll
                    for (int r = 0; r < 4; r++) acc[mt][nt][r] = 0.0f;
        }
    }

    __syncthreads();
    if (tid < 128) {
        int id = (int)(sKey[tid] & 0xFFFFFFFFu);
        sIdx[tid] = id;
        atomicAdd(&g_cnt[id], 1.0f);
    }
    __syncthreads();

    // -------- fused scatter: this CTA's 128 tokens, all 512 channels -----
    {
        const int n  = m0 >> 10;
        const int t0 = m0 & 1023;
        const int tt   = tid & 127;
        const int half = tid >> 7;              // c-offset 0 or 4
        const int idx  = sIdx[tt];
        const float* xb = x + (size_t)n * CC * TT + t0 + tt;
        float* ob = out + OFF_XD + (size_t)n * CC * TT + t0 + tt;
        const float* cbrow = cb + (size_t)idx * CC;
        float* srow = g_sum + (size_t)idx * CC;

        float loss = 0.0f;
        #pragma unroll 8
        for (int k = 0; k < 64; k++) {
            int c = half * 4 + k * 8;
            float4 cv = *(const float4*)(cbrow + c);
            float x0 = __ldcs(xb + (size_t)(c + 0) * TT);
            float x1 = __ldcs(xb + (size_t)(c + 1) * TT);
            float x2 = __ldcs(xb + (size_t)(c + 2) * TT);
            float x3 = __ldcs(xb + (size_t)(c + 3) * TT);
            float d0 = x0 - cv.x, d1 = x1 - cv.y, d2 = x2 - cv.z, d3 = x3 - cv.w;
            loss = fmaf(d0, d0, loss); loss = fmaf(d1, d1, loss);
            loss = fmaf(d2, d2, loss); loss = fmaf(d3, d3, loss);
            __stcs(ob + (size_t)(c + 0) * TT, x0 + (cv.x - x0));
            __stcs(ob + (size_t)(c + 1) * TT, x1 + (cv.y - x1));
            __stcs(ob + (size_t)(c + 2) * TT, x2 + (cv.z - x2));
            __stcs(ob + (size_t)(c + 3) * TT, x3 + (cv.w - x3));
            asm volatile("red.global.add.v4.f32 [%0], {%1, %2, %3, %4};"
                         :: "l"(srow + c), "f"(x0), "f"(x1), "f"(x2), "f"(x3) : "memory");
        }

        sRed[tid] = loss;
        __syncthreads();
        for (int o = 128; o > 0; o >>= 1) {
            if (tid < o) sRed[tid] += sRed[tid + o];
            __syncthreads();
        }
        if (tid == 0) atomicAdd(&g_loss, sRed[0]);
    }
}

// ---------------- EMA + codebook (+ scalars in block 0) ----------------
__global__ __launch_bounds__(256) void k_ema(const float* __restrict__ x,
                                             const float* __restrict__ code_sum_in,
                                             const float* __restrict__ code_count_in,
                                             float* __restrict__ out) {
    const int j   = blockIdx.x;
    const int tid = threadIdx.x;
    const float cnt_new = g_cnt[j];
    const float cema = MU * code_count_in[j] + OMU * cnt_new;
    const bool  usage = (cema >= 1.0f);
    const float den = fmaxf(cema, 1e-10f);
    const int   rn = j >> 10;
    const int   rt = j & 1023;

    for (int c = tid; c < CC; c += 256) {
        float sema = MU * code_sum_in[(size_t)j * CC + c] + OMU * g_sum[(size_t)j * CC + c];
        float upd  = sema / den;
        float repl = x[(size_t)rn * CC * TT + (size_t)c * TT + rt];
        out[OFF_CB   + (size_t)j * CC + c] = usage ? upd : repl;
        out[OFF_SEMA + (size_t)j * CC + c] = sema;
    }
    if (tid == 0) out[OFF_CEMA + j] = cema;

    if (j == 0) {
        __shared__ float sRed[256];
        float s = 0.0f;
        const float inv_total = 1.0f / (32768.0f + 1e-10f);
        for (int q = tid; q < NB; q += 256) {
            float p = g_cnt[q] * inv_total;
            s += p * logf(p + 1e-7f);
        }
        sRed[tid] = s;
        __syncthreads();
        for (int o = 128; o > 0; o >>= 1) {
            if (tid < o) sRed[tid] += sRed[tid + o];
            __syncthreads();
        }
        if (tid == 0) {
            out[OFF_PERP] = expf(-sRed[0]);
            out[OFF_LOSS] = g_loss * (1.0f / 16777216.0f);
        }
    }
}

// ----------------------------------------------------------------
extern "C" void kernel_launch(void* const* d_in, const int* in_sizes, int n_in,
                              void* d_out, int out_size) {
    const float* x             = (const float*)d_in[0];
    const float* codebook      = (const float*)d_in[1];
    const float* code_sum_in   = (const float*)d_in[2];
    const float* code_count_in = (const float*)d_in[3];
    float* out = (float*)d_out;

    cudaFuncSetAttribute(k_hmma, cudaFuncAttributeMaxDynamicSharedMemorySize, HMMA_SMEM);

    {
        const int total = NB * CC + NB + 1;
        k_zero<<<(total + 255) / 256, 256>>>();
    }
    k_convert_x<<<4096, 256>>>(x);
    k_convert_cb<<<256, 256>>>(codebook);
    k_hmma<<<NTOK / 128, 256, HMMA_SMEM>>>(x, codebook, out);
    k_ema<<<NB, 256>>>(x, code_sum_in, code_count_in, out);
}

// round 7
// speedup vs baseline: 1.0299x; 1.0299x over previous
#include <cuda_runtime.h>
#include <cuda_bf16.h>
#include <cstdint>

// Problem constants
#define NN   32
#define CC   512
#define TT   1024
#define NTOK 32768            // NN*TT
#define NB   2048
#define MU   0.99f
#define OMU  0.01f

// Output layout (concatenated, all f32)
#define OFF_XD    ((size_t)0)
#define OFF_LOSS  ((size_t)16777216)
#define OFF_PERP  ((size_t)16777217)
#define OFF_CB    ((size_t)16777218)
#define OFF_SEMA  ((size_t)17825794)
#define OFF_CEMA  ((size_t)18874370)

// ---------------- device scratch (no allocs allowed) ----------------
__device__ float g_cbnorm[NB];
__device__ float g_sum[(size_t)NB * CC];
__device__ float g_cnt[NB];
__device__ float g_loss;
__device__ __align__(16) __nv_bfloat16 g_xhi[(size_t)NTOK * CC];
__device__ __align__(16) __nv_bfloat16 g_xlo[(size_t)NTOK * CC];
__device__ __align__(16) __nv_bfloat16 g_bhi[(size_t)NB * CC];
__device__ __align__(16) __nv_bfloat16 g_blo[(size_t)NB * CC];

// ---------------- PTX helpers (arch-neutral: sm_80-era features only) ----
__device__ __forceinline__ uint32_t smem_u32(const void* p) {
    uint32_t a;
    asm("{ .reg .u64 t; cvta.to.shared.u64 t, %1; cvt.u32.u64 %0, t; }" : "=r"(a) : "l"(p));
    return a;
}
__device__ __forceinline__ void cp16(uint32_t dst, const void* src) {
    asm volatile("cp.async.cg.shared.global [%0], [%1], 16;" :: "r"(dst), "l"(src));
}
__device__ __forceinline__ void ldmx4(uint32_t* r, uint32_t addr) {
    asm volatile("ldmatrix.sync.aligned.m8n8.x4.shared.b16 {%0,%1,%2,%3}, [%4];"
                 : "=r"(r[0]), "=r"(r[1]), "=r"(r[2]), "=r"(r[3]) : "r"(addr));
}
__device__ __forceinline__ void mma16816(float* d, const uint32_t* a, const uint32_t* b) {
    asm volatile(
        "mma.sync.aligned.m16n8k16.row.col.f32.bf16.bf16.f32 "
        "{%0,%1,%2,%3}, {%4,%5,%6,%7}, {%8,%9}, {%0,%1,%2,%3};"
        : "+f"(d[0]), "+f"(d[1]), "+f"(d[2]), "+f"(d[3])
        : "r"(a[0]), "r"(a[1]), "r"(a[2]), "r"(a[3]), "r"(b[0]), "r"(b[1]));
}

// ---------------- zero scratch ----------------
__global__ void k_zero() {
    int i = blockIdx.x * blockDim.x + threadIdx.x;
    const int total = NB * CC + NB + 1;
    for (; i < total; i += gridDim.x * blockDim.x) {
        if (i < NB * CC)           g_sum[i] = 0.0f;
        else if (i < NB * CC + NB) g_cnt[i - NB * CC] = 0.0f;
        else                       g_loss = 0.0f;
    }
}

// ---------------- codebook: bf16 hi/lo split + exact fp32 norms ----------
__global__ __launch_bounds__(256) void k_convert_cb(const float* __restrict__ cb) {
    int wid  = (blockIdx.x * blockDim.x + threadIdx.x) >> 5;
    int lane = threadIdx.x & 31;
    if (wid >= NB) return;
    const float* row = cb + (size_t)wid * CC;
    float s = 0.0f;
    #pragma unroll
    for (int i = 0; i < CC / 32; i++) {
        float v = row[lane + 32 * i];
        s += v * v;
        __nv_bfloat16 hi = __float2bfloat16(v);
        g_bhi[(size_t)wid * CC + lane + 32 * i] = hi;
        g_blo[(size_t)wid * CC + lane + 32 * i] = __float2bfloat16(v - __bfloat162float(hi));
    }
    #pragma unroll
    for (int o = 16; o > 0; o >>= 1) s += __shfl_down_sync(0xFFFFFFFFu, s, o);
    if (lane == 0) g_cbnorm[wid] = s;
}

// ---------------- transpose + bf16 hi/lo split of x ----------------
__global__ __launch_bounds__(256) void k_convert_x(const float* __restrict__ x) {
    __shared__ float s[64][65];
    const int b = blockIdx.x;
    const int ttile = b & 15, ctile = (b >> 4) & 7, n = b >> 7;
    const int c0 = ctile * 64, t0 = ttile * 64;
    const int tid = threadIdx.x;
    const float* xb = x + (size_t)n * CC * TT;
    #pragma unroll
    for (int q = 0; q < 16; q++) {
        int idx = tid + 256 * q;
        int r = idx >> 6, col = idx & 63;
        s[r][col] = xb[(size_t)(c0 + r) * TT + t0 + col];
    }
    __syncthreads();
    #pragma unroll
    for (int q = 0; q < 16; q++) {
        int idx = tid + 256 * q;
        int tr = idx >> 6, cc = idx & 63;
        float v = s[cc][tr];
        __nv_bfloat16 hi = __float2bfloat16(v);
        __nv_bfloat16 lo = __float2bfloat16(v - __bfloat162float(hi));
        size_t token = (size_t)(n * 1024 + t0 + tr);
        g_xhi[token * 512 + c0 + cc] = hi;
        g_xlo[token * 512 + c0 + cc] = lo;
    }
}

// ---------------- mma.sync GEMM + fused argmin + fused scatter ----------
// Block: 128 tokens x 128-code tile, 16 code tiles, K' = 3*512 = 1536.
// 4 warps (2 x 2), warp tile 64x64 => A re-read x2, B x2 (was x4/x2).
// 3-stage cp.async ring, BK = 64. 128 threads, 2 CTAs/SM, ~205 regs.
#define STAGE 32768
#define HMMA_SMEM (3 * STAGE)
#define NSTEPS 384              // 16 nj * 24 k-steps

__device__ __forceinline__ void load_tile(int tid, uint32_t dyn, int it, int m0) {
    const int nj = it / 24;
    const int kt = it - nj * 24;
    const int seg = kt >> 3;
    const int kke = (kt & 7) << 6;    // k element offset within 512
    const __nv_bfloat16* Asrc = ((seg < 2) ? g_xhi : g_xlo) + (size_t)m0 * 512 + kke;
    const __nv_bfloat16* Bsrc = ((seg == 1) ? g_blo : g_bhi) + (size_t)nj * 128 * 512 + kke;
    const uint32_t abase = dyn + (uint32_t)(it % 3) * STAGE;
    const uint32_t bbase = abase + 16384u;
    #pragma unroll
    for (int q = 0; q < 8; q++) {
        int op = tid + 128 * q;
        int row = op >> 3, c = op & 7;
        cp16(abase + row * 128 + (((c ^ row) & 7) << 4), Asrc + (size_t)row * 512 + c * 8);
    }
    #pragma unroll
    for (int q = 0; q < 8; q++) {
        int op = tid + 128 * q;
        int row = op >> 3, c = op & 7;
        cp16(bbase + row * 128 + (((c ^ row) & 7) << 4), Bsrc + (size_t)row * 512 + c * 8);
    }
    asm volatile("cp.async.commit_group;" ::: "memory");
}

__global__ __launch_bounds__(128, 2) void k_hmma(const float* __restrict__ x,
                                                 const float* __restrict__ cb,
                                                 float* __restrict__ out) {
    extern __shared__ char dsm[];
    __shared__ unsigned long long sKey[128];
    __shared__ int   sIdx[128];
    __shared__ float sRed[128];
    const uint32_t dyn = smem_u32(dsm);
    const int tid  = threadIdx.x;
    const int lane = tid & 31;
    const int warp = tid >> 5;
    const int wm   = warp >> 1;      // 0..1
    const int wn   = warp & 1;       // 0..1
    const int m0   = blockIdx.x * 128;

    // ldmatrix per-thread addressing
    const int sub = lane >> 3, l7 = lane & 7;
    const int a_rowadd = ((sub & 1) << 3) + l7;
    const int a_cadd   = sub >> 1;
    const int b_rowadd = ((sub >> 1) << 3) + l7;
    const int b_cadd   = sub & 1;
    uint32_t aRowB[4], bRowB[4];
    #pragma unroll
    for (int mt = 0; mt < 4; mt++) aRowB[mt] = (uint32_t)(wm * 64 + mt * 16 + a_rowadd) * 128u;
    #pragma unroll
    for (int p = 0; p < 4; p++)    bRowB[p] = (uint32_t)(wn * 64 + p * 16 + b_rowadd) * 128u;

    float acc[4][8][4];
    #pragma unroll
    for (int mt = 0; mt < 4; mt++)
        #pragma unroll
        for (int nt = 0; nt < 8; nt++)
            #pragma unroll
            for (int r = 0; r < 4; r++) acc[mt][nt][r] = 0.0f;

    unsigned long long best[8];
    #pragma unroll
    for (int s = 0; s < 8; s++) best[s] = 0xFFFFFFFFFFFFFFFFULL;

    load_tile(tid, dyn, 0, m0);
    load_tile(tid, dyn, 1, m0);

    for (int it = 0; it < NSTEPS; it++) {
        if (it + 1 < NSTEPS) asm volatile("cp.async.wait_group 1;" ::: "memory");
        else                 asm volatile("cp.async.wait_group 0;" ::: "memory");
        __syncthreads();
        if (it + 2 < NSTEPS) load_tile(tid, dyn, it + 2, m0);

        const uint32_t abase = dyn + (uint32_t)(it % 3) * STAGE;
        const uint32_t bbase = abase + 16384u;

        #pragma unroll
        for (int kk = 0; kk < 4; kk++) {
            uint32_t afr[4][4], bfr[4][4];
            #pragma unroll
            for (int mt = 0; mt < 4; mt++)
                ldmx4(afr[mt], abase + aRowB[mt] + ((((kk * 2 + a_cadd) ^ l7) & 7) << 4));
            #pragma unroll
            for (int p = 0; p < 4; p++)
                ldmx4(bfr[p], bbase + bRowB[p] + ((((kk * 2 + b_cadd) ^ l7) & 7) << 4));
            #pragma unroll
            for (int mt = 0; mt < 4; mt++)
                #pragma unroll
                for (int nt = 0; nt < 8; nt++)
                    mma16816(acc[mt][nt], afr[mt], &bfr[nt >> 1][(nt & 1) * 2]);
        }

        // end of one nj code-tile: fold argmin into keys, reset acc
        if (it % 24 == 23) {
            const int njbase = (it / 24) * 128;
            #pragma unroll
            for (int mt = 0; mt < 4; mt++) {
                #pragma unroll
                for (int rh = 0; rh < 2; rh++) {
                    unsigned long long b = best[mt * 2 + rh];
                    #pragma unroll
                    for (int nt = 0; nt < 8; nt++) {
                        #pragma unroll
                        for (int c = 0; c < 2; c++) {
                            int j = njbase + wn * 64 + nt * 8 + ((lane & 3) << 1) + c;
                            float d = fmaf(-2.0f, acc[mt][nt][rh * 2 + c], __ldg(&g_cbnorm[j]));
                            unsigned u = __float_as_uint(d);
                            u = (u & 0x80000000u) ? ~u : (u | 0x80000000u);
                            unsigned long long key =
                                ((unsigned long long)u << 32) | (unsigned)j;
                            b = min(b, key);
                        }
                    }
                    best[mt * 2 + rh] = b;
                }
            }
            #pragma unroll
            for (int mt = 0; mt < 4; mt++)
                #pragma unroll
                for (int nt = 0; nt < 8; nt++)
                    #pragma unroll
                    for (int r = 0; r < 4; r++) acc[mt][nt][r] = 0.0f;
        }
    }

    // final cross-thread argmin reduce
    if (tid < 128) sKey[tid] = 0xFFFFFFFFFFFFFFFFULL;
    __syncthreads();
    #pragma unroll
    for (int s = 0; s < 8; s++) {
        unsigned long long v = best[s];
        v = min(v, __shfl_xor_sync(0xFFFFFFFFu, v, 1));
        v = min(v, __shfl_xor_sync(0xFFFFFFFFu, v, 2));
        if ((lane & 3) == 0) {
            int row = wm * 64 + (s >> 1) * 16 + (lane >> 2) + ((s & 1) << 3);
            atomicMin(&sKey[row], v);
        }
    }
    __syncthreads();
    if (tid < 128) {
        int id = (int)(sKey[tid] & 0xFFFFFFFFu);
        sIdx[tid] = id;
        atomicAdd(&g_cnt[id], 1.0f);
    }
    __syncthreads();

    // -------- fused scatter: this CTA's 128 tokens, all 512 channels -----
    {
        const int n  = m0 >> 10;
        const int t0 = m0 & 1023;
        const int idx  = sIdx[tid];
        const float* xb = x + (size_t)n * CC * TT + t0 + tid;
        float* ob = out + OFF_XD + (size_t)n * CC * TT + t0 + tid;
        const float* cbrow = cb + (size_t)idx * CC;
        float* srow = g_sum + (size_t)idx * CC;

        float loss = 0.0f;
        #pragma unroll 8
        for (int k = 0; k < 128; k++) {
            int c = k * 4;
            float4 cv = *(const float4*)(cbrow + c);
            float x0 = __ldcs(xb + (size_t)(c + 0) * TT);
            float x1 = __ldcs(xb + (size_t)(c + 1) * TT);
            float x2 = __ldcs(xb + (size_t)(c + 2) * TT);
            float x3 = __ldcs(xb + (size_t)(c + 3) * TT);
            float d0 = x0 - cv.x, d1 = x1 - cv.y, d2 = x2 - cv.z, d3 = x3 - cv.w;
            loss = fmaf(d0, d0, loss); loss = fmaf(d1, d1, loss);
            loss = fmaf(d2, d2, loss); loss = fmaf(d3, d3, loss);
            __stcs(ob + (size_t)(c + 0) * TT, x0 + (cv.x - x0));
            __stcs(ob + (size_t)(c + 1) * TT, x1 + (cv.y - x1));
            __stcs(ob + (size_t)(c + 2) * TT, x2 + (cv.z - x2));
            __stcs(ob + (size_t)(c + 3) * TT, x3 + (cv.w - x3));
            asm volatile("red.global.add.v4.f32 [%0], {%1, %2, %3, %4};"
                         :: "l"(srow + c), "f"(x0), "f"(x1), "f"(x2), "f"(x3) : "memory");
        }

        sRed[tid] = loss;
        __syncthreads();
        for (int o = 64; o > 0; o >>= 1) {
            if (tid < o) sRed[tid] += sRed[tid + o];
            __syncthreads();
        }
        if (tid == 0) atomicAdd(&g_loss, sRed[0]);
    }
}

// ---------------- EMA + codebook (+ scalars in block 0) ----------------
__global__ __launch_bounds__(256) void k_ema(const float* __restrict__ x,
                                             const float* __restrict__ code_sum_in,
                                             const float* __restrict__ code_count_in,
                                             float* __restrict__ out) {
    const int j   = blockIdx.x;
    const int tid = threadIdx.x;
    const float cnt_new = g_cnt[j];
    const float cema = MU * code_count_in[j] + OMU * cnt_new;
    const bool  usage = (cema >= 1.0f);
    const float den = fmaxf(cema, 1e-10f);
    const int   rn = j >> 10;
    const int   rt = j & 1023;

    for (int c = tid; c < CC; c += 256) {
        float sema = MU * code_sum_in[(size_t)j * CC + c] + OMU * g_sum[(size_t)j * CC + c];
        float upd  = sema / den;
        float repl = x[(size_t)rn * CC * TT + (size_t)c * TT + rt];
        out[OFF_CB   + (size_t)j * CC + c] = usage ? upd : repl;
        out[OFF_SEMA + (size_t)j * CC + c] = sema;
    }
    if (tid == 0) out[OFF_CEMA + j] = cema;

    if (j == 0) {
        __shared__ float sRed[256];
        float s = 0.0f;
        const float inv_total = 1.0f / (32768.0f + 1e-10f);
        for (int q = tid; q < NB; q += 256) {
            float p = g_cnt[q] * inv_total;
            s += p * logf(p + 1e-7f);
        }
        sRed[tid] = s;
        __syncthreads();
        for (int o = 128; o > 0; o >>= 1) {
            if (tid < o) sRed[tid] += sRed[tid + o];
            __syncthreads();
        }
        if (tid == 0) {
            out[OFF_PERP] = expf(-sRed[0]);
            out[OFF_LOSS] = g_loss * (1.0f / 16777216.0f);
        }
    }
}

// ----------------------------------------------------------------
extern "C" void kernel_launch(void* const* d_in, const int* in_sizes, int n_in,
                              void* d_out, int out_size) {
    const float* x             = (const float*)d_in[0];
    const float* codebook      = (const float*)d_in[1];
    const float* code_sum_in   = (const float*)d_in[2];
    const float* code_count_in = (const float*)d_in[3];
    float* out = (float*)d_out;

    cudaFuncSetAttribute(k_hmma, cudaFuncAttributeMaxDynamicSharedMemorySize, HMMA_SMEM);

    {
        const int total = NB * CC + NB + 1;
        k_zero<<<(total + 255) / 256, 256>>>();
    }
    k_convert_x<<<4096, 256>>>(x);
    k_convert_cb<<<256, 256>>>(codebook);
    k_hmma<<<NTOK / 128, 128, HMMA_SMEM>>>(x, codebook, out);
    k_ema<<<NB, 256>>>(x, code_sum_in, code_count_in, out);
}

// round 8
// speedup vs baseline: 1.2500x; 1.2137x over previous
#include <cuda_runtime.h>
#include <cuda_bf16.h>
#include <cstdint>

// Problem constants
#define NN   32
#define CC   512
#define TT   1024
#define NTOK 32768            // NN*TT
#define NB   2048
#define MU   0.99f
#define OMU  0.01f
#define MARGIN 12.0f
#define LCAP 2048

// Output layout (concatenated, all f32)
#define OFF_XD    ((size_t)0)
#define OFF_LOSS  ((size_t)16777216)
#define OFF_PERP  ((size_t)16777217)
#define OFF_CB    ((size_t)16777218)
#define OFF_SEMA  ((size_t)17825794)
#define OFF_CEMA  ((size_t)18874370)

// ---------------- device scratch (no allocs allowed) ----------------
__device__ float g_cbnorm[NB];
__device__ float g_sum[(size_t)NB * CC];
__device__ float g_cnt[NB];
__device__ float g_loss;
__device__ __align__(16) __nv_bfloat16 g_xhi[(size_t)NTOK * CC];
__device__ __align__(16) float         g_xT [(size_t)NTOK * CC];   // fp32 transposed x
__device__ __align__(16) __nv_bfloat16 g_bhi[(size_t)NB * CC];

// ---------------- PTX helpers ----------------
__device__ __forceinline__ uint32_t smem_u32(const void* p) {
    uint32_t a;
    asm("{ .reg .u64 t; cvta.to.shared.u64 t, %1; cvt.u32.u64 %0, t; }" : "=r"(a) : "l"(p));
    return a;
}
__device__ __forceinline__ void cp16(uint32_t dst, const void* src) {
    asm volatile("cp.async.cg.shared.global [%0], [%1], 16;" :: "r"(dst), "l"(src));
}
__device__ __forceinline__ void ldmx4(uint32_t* r, uint32_t addr) {
    asm volatile("ldmatrix.sync.aligned.m8n8.x4.shared.b16 {%0,%1,%2,%3}, [%4];"
                 : "=r"(r[0]), "=r"(r[1]), "=r"(r[2]), "=r"(r[3]) : "r"(addr));
}
__device__ __forceinline__ void mma16816(float* d, const uint32_t* a, const uint32_t* b) {
    asm volatile(
        "mma.sync.aligned.m16n8k16.row.col.f32.bf16.bf16.f32 "
        "{%0,%1,%2,%3}, {%4,%5,%6,%7}, {%8,%9}, {%0,%1,%2,%3};"
        : "+f"(d[0]), "+f"(d[1]), "+f"(d[2]), "+f"(d[3])
        : "r"(a[0]), "r"(a[1]), "r"(a[2]), "r"(a[3]), "r"(b[0]), "r"(b[1]));
}
// order-preserving float<->uint
__device__ __forceinline__ unsigned f2u(float f) {
    unsigned u = __float_as_uint(f);
    return (u & 0x80000000u) ? ~u : (u | 0x80000000u);
}
__device__ __forceinline__ float u2f(unsigned u) {
    return (u & 0x80000000u) ? __uint_as_float(u & 0x7FFFFFFFu)
                             : __uint_as_float(~u);
}

// ---------------- zero scratch ----------------
__global__ void k_zero() {
    int i = blockIdx.x * blockDim.x + threadIdx.x;
    const int total = NB * CC + NB + 1;
    for (; i < total; i += gridDim.x * blockDim.x) {
        if (i < NB * CC)           g_sum[i] = 0.0f;
        else if (i < NB * CC + NB) g_cnt[i - NB * CC] = 0.0f;
        else                       g_loss = 0.0f;
    }
}

// ---------------- codebook: bf16 hi + exact fp32 norms ----------
__global__ __launch_bounds__(256) void k_convert_cb(const float* __restrict__ cb) {
    int wid  = (blockIdx.x * blockDim.x + threadIdx.x) >> 5;
    int lane = threadIdx.x & 31;
    if (wid >= NB) return;
    const float* row = cb + (size_t)wid * CC;
    float s = 0.0f;
    #pragma unroll
    for (int i = 0; i < CC / 32; i++) {
        float v = row[lane + 32 * i];
        s += v * v;
        g_bhi[(size_t)wid * CC + lane + 32 * i] = __float2bfloat16(v);
    }
    #pragma unroll
    for (int o = 16; o > 0; o >>= 1) s += __shfl_down_sync(0xFFFFFFFFu, s, o);
    if (lane == 0) g_cbnorm[wid] = s;
}

// ---------------- transpose x: bf16 hi + fp32 copy ----------------
__global__ __launch_bounds__(256) void k_convert_x(const float* __restrict__ x) {
    __shared__ float s[64][65];
    const int b = blockIdx.x;
    const int ttile = b & 15, ctile = (b >> 4) & 7, n = b >> 7;
    const int c0 = ctile * 64, t0 = ttile * 64;
    const int tid = threadIdx.x;
    const float* xb = x + (size_t)n * CC * TT;
    #pragma unroll
    for (int q = 0; q < 16; q++) {
        int idx = tid + 256 * q;
        int r = idx >> 6, col = idx & 63;
        s[r][col] = xb[(size_t)(c0 + r) * TT + t0 + col];
    }
    __syncthreads();
    #pragma unroll
    for (int q = 0; q < 16; q++) {
        int idx = tid + 256 * q;
        int tr = idx >> 6, cc = idx & 63;
        float v = s[cc][tr];
        size_t token = (size_t)(n * 1024 + t0 + tr);
        g_xhi[token * 512 + c0 + cc] = __float2bfloat16(v);
        g_xT [token * 512 + c0 + cc] = v;
    }
}

// ---------------- approx GEMM + candidate collect + exact rescore + scatter
// Block: 128 tokens x 128-code tile, 16 code tiles, K = 512 (hi only).
// 4 warps (2x2), warp tile 64x64. 3-stage cp.async ring, BK = 64.
#define STAGE 32768
#define HMMA_SMEM (3 * STAGE)
#define NSTEPS 128              // 16 nj * 8 k-steps

__device__ __forceinline__ void load_tile(int tid, uint32_t dyn, int it, int m0) {
    const int nj = it >> 3;
    const int kt = it & 7;
    const __nv_bfloat16* Asrc = g_xhi + (size_t)m0 * 512 + kt * 64;
    const __nv_bfloat16* Bsrc = g_bhi + (size_t)nj * 128 * 512 + kt * 64;
    const uint32_t abase = dyn + (uint32_t)(it % 3) * STAGE;
    const uint32_t bbase = abase + 16384u;
    #pragma unroll
    for (int q = 0; q < 8; q++) {
        int op = tid + 128 * q;
        int row = op >> 3, c = op & 7;
        cp16(abase + row * 128 + (((c ^ row) & 7) << 4), Asrc + (size_t)row * 512 + c * 8);
    }
    #pragma unroll
    for (int q = 0; q < 8; q++) {
        int op = tid + 128 * q;
        int row = op >> 3, c = op & 7;
        cp16(bbase + row * 128 + (((c ^ row) & 7) << 4), Bsrc + (size_t)row * 512 + c * 8);
    }
    asm volatile("cp.async.commit_group;" ::: "memory");
}

__global__ __launch_bounds__(128, 2) void k_hmma(const float* __restrict__ x,
                                                 const float* __restrict__ cb,
                                                 float* __restrict__ out) {
    extern __shared__ char dsm[];
    __shared__ unsigned sMinU[128];            // running approx min (ordered uint)
    __shared__ unsigned long long sKeyE[128];  // exact (d,j) keys
    __shared__ unsigned sList[LCAP];           // candidates: row<<16 | j
    __shared__ int  sCnt;
    __shared__ int  sIdx[128];
    __shared__ float sRed[128];

    const uint32_t dyn = smem_u32(dsm);
    const int tid  = threadIdx.x;
    const int lane = tid & 31;
    const int warp = tid >> 5;
    const int wm   = warp >> 1;      // 0..1
    const int wn   = warp & 1;       // 0..1
    const int m0   = blockIdx.x * 128;

    // init shared state
    sMinU[tid] = 0xFFFFFFFFu;
    sKeyE[tid] = 0xFFFFFFFFFFFFFFFFULL;
    if (tid == 0) sCnt = 0;

    // ldmatrix per-thread addressing
    const int sub = lane >> 3, l7 = lane & 7;
    const int a_rowadd = ((sub & 1) << 3) + l7;
    const int a_cadd   = sub >> 1;
    const int b_rowadd = ((sub >> 1) << 3) + l7;
    const int b_cadd   = sub & 1;
    uint32_t aRowB[4], bRowB[4];
    #pragma unroll
    for (int mt = 0; mt < 4; mt++) aRowB[mt] = (uint32_t)(wm * 64 + mt * 16 + a_rowadd) * 128u;
    #pragma unroll
    for (int p = 0; p < 4; p++)    bRowB[p] = (uint32_t)(wn * 64 + p * 16 + b_rowadd) * 128u;

    float acc[4][8][4];
    #pragma unroll
    for (int mt = 0; mt < 4; mt++)
        #pragma unroll
        for (int nt = 0; nt < 8; nt++)
            #pragma unroll
            for (int r = 0; r < 4; r++) acc[mt][nt][r] = 0.0f;

    load_tile(tid, dyn, 0, m0);
    load_tile(tid, dyn, 1, m0);

    for (int it = 0; it < NSTEPS; it++) {
        if (it + 1 < NSTEPS) asm volatile("cp.async.wait_group 1;" ::: "memory");
        else                 asm volatile("cp.async.wait_group 0;" ::: "memory");
        __syncthreads();
        if (it + 2 < NSTEPS) load_tile(tid, dyn, it + 2, m0);

        const uint32_t abase = dyn + (uint32_t)(it % 3) * STAGE;
        const uint32_t bbase = abase + 16384u;

        #pragma unroll
        for (int kk = 0; kk < 4; kk++) {
            uint32_t afr[4][4], bfr[4][4];
            #pragma unroll
            for (int mt = 0; mt < 4; mt++)
                ldmx4(afr[mt], abase + aRowB[mt] + ((((kk * 2 + a_cadd) ^ l7) & 7) << 4));
            #pragma unroll
            for (int p = 0; p < 4; p++)
                ldmx4(bfr[p], bbase + bRowB[p] + ((((kk * 2 + b_cadd) ^ l7) & 7) << 4));
            #pragma unroll
            for (int mt = 0; mt < 4; mt++)
                #pragma unroll
                for (int nt = 0; nt < 8; nt++)
                    mma16816(acc[mt][nt], afr[mt], &bfr[nt >> 1][(nt & 1) * 2]);
        }

        // end of one nj code-tile: fold approx min, then collect candidates
        if ((it & 7) == 7) {
            const int njbase = (it >> 3) * 128;
            float dv[4][8][2];
            // fold this tile's min into sMinU
            #pragma unroll
            for (int mt = 0; mt < 4; mt++) {
                #pragma unroll
                for (int rh = 0; rh < 2; rh++) {
                    unsigned bu = 0xFFFFFFFFu;
                    #pragma unroll
                    for (int nt = 0; nt < 8; nt++) {
                        #pragma unroll
                        for (int c = 0; c < 2; c++) {
                            int j = njbase + wn * 64 + nt * 8 + ((lane & 3) << 1) + c;
                            float d = fmaf(-2.0f, acc[mt][nt][rh * 2 + c], __ldg(&g_cbnorm[j]));
                            dv[mt][nt][c] = d;   // note: indexed [mt][nt][c] for rh loop below
                            bu = min(bu, f2u(d));
                        }
                    }
                    bu = min(bu, __shfl_xor_sync(0xFFFFFFFFu, bu, 1));
                    bu = min(bu, __shfl_xor_sync(0xFFFFFFFFu, bu, 2));
                    if ((lane & 3) == 0) {
                        int row = wm * 64 + mt * 16 + rh * 8 + (lane >> 2);
                        atomicMin(&sMinU[row], bu);
                    }
                    __syncwarp();
                    // dv only holds one rh at a time: collect for this rh after block barrier
                    // => instead store d recomputed below; keep simple: collect inside rh loop
                    // (need block barrier first — handled by recompute approach below)
                }
            }
            __syncthreads();   // all sMinU updates visible
            // collect candidates (recompute d from acc)
            #pragma unroll
            for (int mt = 0; mt < 4; mt++) {
                #pragma unroll
                for (int rh = 0; rh < 2; rh++) {
                    int row = wm * 64 + mt * 16 + rh * 8 + (lane >> 2);
                    float thr = u2f(sMinU[row]) + MARGIN;
                    #pragma unroll
                    for (int nt = 0; nt < 8; nt++) {
                        #pragma unroll
                        for (int c = 0; c < 2; c++) {
                            int j = njbase + wn * 64 + nt * 8 + ((lane & 3) << 1) + c;
                            float d = fmaf(-2.0f, acc[mt][nt][rh * 2 + c], __ldg(&g_cbnorm[j]));
                            if (d <= thr) {
                                int pos = atomicAdd(&sCnt, 1);
                                if (pos < LCAP)
                                    sList[pos] = ((unsigned)row << 16) | (unsigned)j;
                            }
                        }
                    }
                }
            }
            #pragma unroll
            for (int mt = 0; mt < 4; mt++)
                #pragma unroll
                for (int nt = 0; nt < 8; nt++)
                    #pragma unroll
                    for (int r = 0; r < 4; r++) acc[mt][nt][r] = 0.0f;
        }
    }

    __syncthreads();
    // -------- pass 2: exact fp32 rescore of candidates ------------------
    {
        const int cnt = min(sCnt, LCAP);
        for (int i = warp; i < cnt; i += 4) {
            unsigned e = sList[i];
            int row = e >> 16;
            int j   = e & 0xFFFF;
            const float4* xr = (const float4*)(g_xT + (size_t)(m0 + row) * 512);
            const float4* cr = (const float4*)(cb  + (size_t)j * 512);
            float s = 0.0f;
            #pragma unroll
            for (int q = 0; q < 4; q++) {
                float4 a = xr[lane + 32 * q];
                float4 b = cr[lane + 32 * q];
                s += a.x * b.x + a.y * b.y + a.z * b.z + a.w * b.w;
            }
            #pragma unroll
            for (int o = 16; o > 0; o >>= 1) s += __shfl_xor_sync(0xFFFFFFFFu, s, o);
            if (lane == 0) {
                float d = fmaf(-2.0f, s, g_cbnorm[j]);
                unsigned long long key = ((unsigned long long)f2u(d) << 32) | (unsigned)j;
                atomicMin(&sKeyE[row], key);
            }
        }
    }
    __syncthreads();
    {
        int id = (int)(sKeyE[tid] & 0xFFFFFFFFu);
        sIdx[tid] = id;
        atomicAdd(&g_cnt[id], 1.0f);
    }
    __syncthreads();

    // -------- fused scatter: this CTA's 128 tokens, all 512 channels -----
    {
        const int n  = m0 >> 10;
        const int t0 = m0 & 1023;
        const int idx  = sIdx[tid];
        const float* xb = x + (size_t)n * CC * TT + t0 + tid;
        float* ob = out + OFF_XD + (size_t)n * CC * TT + t0 + tid;
        const float* cbrow = cb + (size_t)idx * CC;
        float* srow = g_sum + (size_t)idx * CC;

        float loss = 0.0f;
        #pragma unroll 8
        for (int k = 0; k < 128; k++) {
            int c = k * 4;
            float4 cv = *(const float4*)(cbrow + c);
            float x0 = __ldcs(xb + (size_t)(c + 0) * TT);
            float x1 = __ldcs(xb + (size_t)(c + 1) * TT);
            float x2 = __ldcs(xb + (size_t)(c + 2) * TT);
            float x3 = __ldcs(xb + (size_t)(c + 3) * TT);
            float d0 = x0 - cv.x, d1 = x1 - cv.y, d2 = x2 - cv.z, d3 = x3 - cv.w;
            loss = fmaf(d0, d0, loss); loss = fmaf(d1, d1, loss);
            loss = fmaf(d2, d2, loss); loss = fmaf(d3, d3, loss);
            __stcs(ob + (size_t)(c + 0) * TT, x0 + (cv.x - x0));
            __stcs(ob + (size_t)(c + 1) * TT, x1 + (cv.y - x1));
            __stcs(ob + (size_t)(c + 2) * TT, x2 + (cv.z - x2));
            __stcs(ob + (size_t)(c + 3) * TT, x3 + (cv.w - x3));
            asm volatile("red.global.add.v4.f32 [%0], {%1, %2, %3, %4};"
                         :: "l"(srow + c), "f"(x0), "f"(x1), "f"(x2), "f"(x3) : "memory");
        }

        sRed[tid] = loss;
        __syncthreads();
        for (int o = 64; o > 0; o >>= 1) {
            if (tid < o) sRed[tid] += sRed[tid + o];
            __syncthreads();
        }
        if (tid == 0) atomicAdd(&g_loss, sRed[0]);
    }
}

// ---------------- EMA + codebook (+ scalars in block 0) ----------------
__global__ __launch_bounds__(256) void k_ema(const float* __restrict__ x,
                                             const float* __restrict__ code_sum_in,
                                             const float* __restrict__ code_count_in,
                                             float* __restrict__ out) {
    const int j   = blockIdx.x;
    const int tid = threadIdx.x;
    const float cnt_new = g_cnt[j];
    const float cema = MU * code_count_in[j] + OMU * cnt_new;
    const bool  usage = (cema >= 1.0f);
    const float den = fmaxf(cema, 1e-10f);
    const int   rn = j >> 10;
    const int   rt = j & 1023;

    for (int c = tid; c < CC; c += 256) {
        float sema = MU * code_sum_in[(size_t)j * CC + c] + OMU * g_sum[(size_t)j * CC + c];
        float upd  = sema / den;
        float repl = x[(size_t)rn * CC * TT + (size_t)c * TT + rt];
        out[OFF_CB   + (size_t)j * CC + c] = usage ? upd : repl;
        out[OFF_SEMA + (size_t)j * CC + c] = sema;
    }
    if (tid == 0) out[OFF_CEMA + j] = cema;

    if (j == 0) {
        __shared__ float sRed[256];
        float s = 0.0f;
        const float inv_total = 1.0f / (32768.0f + 1e-10f);
        for (int q = tid; q < NB; q += 256) {
            float p = g_cnt[q] * inv_total;
            s += p * logf(p + 1e-7f);
        }
        sRed[tid] = s;
        __syncthreads();
        for (int o = 128; o > 0; o >>= 1) {
            if (tid < o) sRed[tid] += sRed[tid + o];
            __syncthreads();
        }
        if (tid == 0) {
            out[OFF_PERP] = expf(-sRed[0]);
            out[OFF_LOSS] = g_loss * (1.0f / 16777216.0f);
        }
    }
}

// ----------------------------------------------------------------
extern "C" void kernel_launch(void* const* d_in, const int* in_sizes, int n_in,
                              void* d_out, int out_size) {
    const float* x             = (const float*)d_in[0];
    const float* codebook      = (const float*)d_in[1];
    const float* code_sum_in   = (const float*)d_in[2];
    const float* code_count_in = (const float*)d_in[3];
    float* out = (float*)d_out;

    cudaFuncSetAttribute(k_hmma, cudaFuncAttributeMaxDynamicSharedMemorySize, HMMA_SMEM);

    {
        const int total = NB * CC + NB + 1;
        k_zero<<<(total + 255) / 256, 256>>>();
    }
    k_convert_x<<<4096, 256>>>(x);
    k_convert_cb<<<256, 256>>>(codebook);
    k_hmma<<<NTOK / 128, 128, HMMA_SMEM>>>(x, codebook, out);
    k_ema<<<NB, 256>>>(x, code_sum_in, code_count_in, out);
}